// round 8
// baseline (speedup 1.0000x reference)
#include <cuda_runtime.h>
#include <cuda_bf16.h>
#include <cstdint>

#define KN    8192
#define KD    8
#define NTHR  256
#define IPT   2
#define ITILE 512            // i-rows per dom block (IPT * NTHR)
#define TJ    128            // j-rows per shared tile
#define NSEG  8
#define SEGSZ 1024
#define NTILES 544           // sum_{ti=0..15} 4*(ti+1)

// Device-global scratch. Statics start zeroed; every consumer re-zeroes or
// fully overwrites what it reads -> graph replays are deterministic.
__device__ unsigned       g_keys[16][KN];        // [m*8+d] segment-sorted keys
__device__ int            g_kidx[16][KN];        // original row id per seg-sorted pos
__device__ unsigned short g_rank16[2][KN][KD];   // per-row per-dim rank
__device__ uint4          g_prow[2][KN];         // packed fp16 rank rows, sorted by d0 rank
__device__ int            g_counts[2 * KN];      // per sorted-row "neg" counts
__device__ int            g_hd[KN];              // signed diff histogram (A minus B)
__device__ unsigned       g_ctr;                 // finh arrival counter

__device__ __forceinline__ unsigned f2sortable(float f) {
    unsigned u = __float_as_uint(f);
    return (u & 0x80000000u) ? ~u : (u | 0x80000000u);
}

// packed fp16x2 add (sign-exact for rank differences)
__device__ __forceinline__ unsigned hadd2(unsigned a, unsigned b) {
    unsigned d;
    asm("add.rn.f16x2 %0, %1, %2;" : "=r"(d) : "r"(a), "r"(b));
    return d;
}

// ---------------------------------------------------------------------------
// S1) bitonic-sort 1024-element segments of column d of matrix m.
//     64-bit (key<<32 | idx); distances <=16 run as register shfl passes.
// ---------------------------------------------------------------------------
__global__ __launch_bounds__(SEGSZ) void kdm_sort_seg(const float* __restrict__ X,
                                                      const float* __restrict__ Xh) {
    const int md = blockIdx.y;
    const int d  = md & 7;
    const float* __restrict__ src = (md >> 3) ? Xh : X;
    __shared__ unsigned long long s[SEGSZ];   // 8 KB
    const int tid = threadIdx.x;
    const int e0  = blockIdx.x * SEGSZ;

    s[tid] = ((unsigned long long)f2sortable(src[(size_t)(e0 + tid) * KD + d]) << 32)
             | (unsigned)(e0 + tid);
    __syncthreads();

    for (int k = 2; k <= SEGSZ; k <<= 1) {
        const bool up = (tid & k) == 0;
        for (int j = k >> 1; j >= 32; j >>= 1) {
            const int ixj = tid ^ j;
            if (ixj > tid) {
                const unsigned long long a = s[tid], b = s[ixj];
                if ((a > b) == up) { s[tid] = b; s[ixj] = a; }
            }
            __syncthreads();
        }
        unsigned long long v = s[tid];
        #pragma unroll
        for (int j = 16; j >= 1; j >>= 1) {
            if (j <= (k >> 1)) {
                const unsigned long long o = __shfl_xor_sync(0xffffffffu, v, j);
                const bool keepmin = (((tid & j) == 0) == up);
                const bool omin = (o < v);
                v = (keepmin == omin) ? o : v;
            }
        }
        s[tid] = v;
        __syncthreads();
    }
    const unsigned long long r = s[tid];
    g_keys[md][e0 + tid] = (unsigned)(r >> 32);
    g_kidx[md][e0 + tid] = (int)(unsigned)r;
}

// ---------------------------------------------------------------------------
// S2) global rank per column via cross-segment binary search; scatter 16-bit
//     rank to the element's original row. grid = (KN/256, 16).
// ---------------------------------------------------------------------------
__global__ __launch_bounds__(256) void kdm_rank() {
    const int md = blockIdx.y;
    __shared__ unsigned sk[KN];   // 32 KB
    for (int k = threadIdx.x; k < KN; k += 256) sk[k] = g_keys[md][k];
    __syncthreads();

    const int e   = blockIdx.x * 256 + threadIdx.x;
    const int s   = e >> 10;
    const int pos = e & (SEGSZ - 1);
    const unsigned key = sk[e];

    int rank = pos;
    #pragma unroll
    for (int t = 0; t < NSEG; t++) {
        if (t == s) continue;
        const unsigned* seg = sk + t * SEGSZ;
        int lo = 0, hi = SEGSZ;
        if (t < s) {
            while (lo < hi) { const int mid = (lo + hi) >> 1; if (seg[mid] <= key) lo = mid + 1; else hi = mid; }
        } else {
            while (lo < hi) { const int mid = (lo + hi) >> 1; if (seg[mid] <  key) lo = mid + 1; else hi = mid; }
        }
        rank += lo;
    }
    g_rank16[md >> 3][g_kidx[md][e]][md & 7] = (unsigned short)rank;
}

// ---------------------------------------------------------------------------
// S3) pack dims 1..7 ranks (+0x400 fp16 bias) into a uint4 at the row's
//     d0-rank position. grid = (KN/256, 2).
// ---------------------------------------------------------------------------
__global__ __launch_bounds__(256) void kdm_pack() {
    const int m   = blockIdx.y;
    const int row = blockIdx.x * 256 + threadIdx.x;
    const uint4 q = *reinterpret_cast<const uint4*>(&g_rank16[m][row][0]);
    const unsigned OFF = 0x04000400u;
    const unsigned d0 = q.x & 0xffffu;
    uint4 o;
    o.x = ((q.x >> 16) | (q.y << 16)) + OFF;   // d1, d2
    o.y = ((q.y >> 16) | (q.z << 16)) + OFF;   // d3, d4
    o.z = ((q.z >> 16) | (q.w << 16)) + OFF;   // d5, d6
    o.w = ( q.w >> 16)                + OFF;   // d7, pad
    g_prow[m][d0] = o;
}

// ---------------------------------------------------------------------------
// D) triangular dominance on rank-sorted packed rows. Thread owns 2 i-rows
//    (ITILE=512 strips -> 6.25% diagonal waste). Strip ti has 4*(ti+1)
//    j-tiles of 128; start(ti) = 2*ti*(ti+1).
// ---------------------------------------------------------------------------
__global__ __launch_bounds__(NTHR, 8) void kdm_dom() {
    const int m = blockIdx.y;
    const int b = blockIdx.x;
    int ti = (int)((sqrtf(2.0f * (float)b + 1.0f) - 1.0f) * 0.5f);
    while (2 * ti * (ti + 1) > b) --ti;
    while (2 * (ti + 1) * (ti + 2) <= b) ++ti;
    const int tj = b - 2 * ti * (ti + 1);
    const int i0 = ti << 9;
    const int j0 = tj << 7;

    __shared__ uint4 sj[TJ];    // 2 KB, fp16-negated j-rows

    if (threadIdx.x < TJ) {
        uint4 v = g_prow[m][j0 + threadIdx.x];
        v.x ^= 0x80008000u; v.y ^= 0x80008000u;
        v.z ^= 0x80008000u; v.w ^= 0x80008000u;
        sj[threadIdx.x] = v;
    }

    const int ib = i0 + threadIdx.x;
    uint4 a[IPT];
    #pragma unroll
    for (int p = 0; p < IPT; p++) a[p] = g_prow[m][ib + p * NTHR];
    __syncthreads();

    unsigned neg[IPT] = {0, 0};

    if (j0 + TJ <= i0) {
        #pragma unroll 4
        for (int j = 0; j < TJ; j++) {
            const uint4 bv = sj[j];
            #pragma unroll
            for (int p = 0; p < IPT; p++) {
                const unsigned x0 = hadd2(a[p].x, bv.x);
                const unsigned x1 = hadd2(a[p].y, bv.y);
                const unsigned x2 = hadd2(a[p].z, bv.z);
                const unsigned x3 = hadd2(a[p].w, bv.w);
                const unsigned o  = x0 | x1 | x2;
                const unsigned sb = (o | x3) & 0x80008000u;   // LOP3 w/ pred-out
                if (sb) neg[p]++;                             // predicated IADD
            }
        }
    } else {
        int lim[IPT];
        #pragma unroll
        for (int p = 0; p < IPT; p++) lim[p] = ib + p * NTHR - j0;
        #pragma unroll 4
        for (int j = 0; j < TJ; j++) {
            const uint4 bv = sj[j];
            #pragma unroll
            for (int p = 0; p < IPT; p++) {
                const unsigned x0 = hadd2(a[p].x, bv.x);
                const unsigned x1 = hadd2(a[p].y, bv.y);
                const unsigned x2 = hadd2(a[p].z, bv.z);
                const unsigned x3 = hadd2(a[p].w, bv.w);
                const unsigned o  = x0 | x1 | x2;
                const unsigned sb = (o | x3) & 0x80008000u;
                neg[p] += min(sb, 1u) | (unsigned)(j >= lim[p]);
            }
        }
    }

    #pragma unroll
    for (int p = 0; p < IPT; p++)
        atomicAdd(&g_counts[m * KN + ib + p * NTHR], (int)neg[p]);
}

// ---------------------------------------------------------------------------
// FH) fused histogram + finalize. 16 blocks histogram into g_hd with
//     warp-aggregated atomics; the LAST block to arrive runs the W1 scan.
//     Result independent of arrival order -> deterministic. Re-zeroes all
//     scratch it consumed.
// ---------------------------------------------------------------------------
__global__ __launch_bounds__(1024) void kdm_finh(float* __restrict__ out) {
    const int tid = threadIdx.x, lane = tid & 31, wid = tid >> 5;

    {   // histogram phase
        const int slot = blockIdx.x * 1024 + tid;
        const int neg  = g_counts[slot];
        g_counts[slot] = 0;
        const int i = slot & (KN - 1);
        const int v = (((i >> 9) + 1) << 9) - neg;   // dominated count
        const int delta = (slot >= KN) ? -1 : 1;
        const unsigned mask = __match_any_sync(0xffffffffu, v);
        if ((int)(__ffs(mask) - 1) == lane)
            atomicAdd(&g_hd[v], delta * __popc(mask));
    }

    __threadfence();
    __syncthreads();
    __shared__ bool s_last;
    if (tid == 0) s_last = (atomicAdd(&g_ctr, 1u) == gridDim.x - 1);
    __syncthreads();
    if (!s_last) return;
    __threadfence();   // acquire all blocks' g_hd updates

    // ---- finalize (only in the last-arriving block) ----
    __shared__ int wsum[32];
    const int base = tid * 8;
    int d[8], tot = 0;
    #pragma unroll
    for (int k = 0; k < 8; k++) {
        d[k] = g_hd[base + k];
        g_hd[base + k] = 0;
        tot += d[k];
    }

    int v = tot;
    #pragma unroll
    for (int off = 1; off < 32; off <<= 1) {
        const int n = __shfl_up_sync(0xffffffffu, v, off);
        if (lane >= off) v += n;
    }
    if (lane == 31) wsum[wid] = v;
    __syncthreads();
    if (wid == 0) {
        int w = wsum[lane];
        #pragma unroll
        for (int off = 1; off < 32; off <<= 1) {
            const int n = __shfl_up_sync(0xffffffffu, w, off);
            if (lane >= off) w += n;
        }
        wsum[lane] = w;
    }
    __syncthreads();

    const int excl = v - tot + (wid ? wsum[wid - 1] : 0);
    int run = excl, acc = 0;
    #pragma unroll
    for (int k = 0; k < 8; k++) {
        run += d[k];
        acc += (run >= 0) ? run : -run;
    }

    #pragma unroll
    for (int off = 16; off; off >>= 1) acc += __shfl_down_sync(0xffffffffu, acc, off);
    __syncthreads();
    if (lane == 0) wsum[wid] = acc;
    __syncthreads();
    if (wid == 0) {
        int r = wsum[lane];
        #pragma unroll
        for (int off = 16; off; off >>= 1) r += __shfl_down_sync(0xffffffffu, r, off);
        if (lane == 0) {
            out[0] = (float)r / ((float)KN * (float)(KN - 1));
            g_ctr = 0;   // reset for next graph replay
        }
    }
}

// ---------------------------------------------------------------------------
extern "C" void kernel_launch(void* const* d_in, const int* in_sizes, int n_in,
                              void* d_out, int out_size) {
    const float* X  = (const float*)d_in[0];
    const float* Xh = (const float*)d_in[1];
    float* out = (float*)d_out;

    kdm_sort_seg<<<dim3(NSEG, 16),     SEGSZ>>>(X, Xh);
    kdm_rank    <<<dim3(KN / 256, 16), 256  >>>();
    kdm_pack    <<<dim3(KN / 256, 2),  256  >>>();
    kdm_dom     <<<dim3(NTILES, 2),    NTHR >>>();
    kdm_finh    <<<2 * KN / 1024,      1024 >>>(out);
}

// round 10
// speedup vs baseline: 1.0533x; 1.0533x over previous
#include <cuda_runtime.h>
#include <cuda_bf16.h>
#include <cstdint>

#define KN    8192
#define KD    8
#define NTHR  256
#define IPT   4
#define ITILE 1024           // i-rows per dom block (IPT * NTHR)
#define TJ    64             // j-rows per shared tile
#define NSEG  8
#define SEGSZ 1024
#define NTILES 576           // sum_{ti=0..7} 16*(ti+1)

// Device-global scratch. Statics start zeroed; every consumer re-zeroes or
// fully overwrites what it reads -> graph replays are deterministic.
__device__ unsigned       g_keys[16][KN];        // [m*8+d] segment-sorted keys
__device__ int            g_kidx[16][KN];        // original row id per seg-sorted pos
__device__ unsigned short g_rank16[2][KN][KD];   // per-row per-dim rank
__device__ uint4          g_prow[2][KN];         // packed fp16 rank rows, sorted by d0 rank
__device__ int            g_counts[2 * KN];      // per sorted-row "neg" counts
__device__ int            g_hd[KN];              // signed diff histogram (A minus B)
__device__ unsigned       g_ctr;                 // finh arrival counter

__device__ __forceinline__ unsigned f2sortable(float f) {
    unsigned u = __float_as_uint(f);
    return (u & 0x80000000u) ? ~u : (u | 0x80000000u);
}

// packed fp16x2 add (sign-exact for rank differences)
__device__ __forceinline__ unsigned hadd2(unsigned a, unsigned b) {
    unsigned d;
    asm("add.rn.f16x2 %0, %1, %2;" : "=r"(d) : "r"(a), "r"(b));
    return d;
}

// ---------------------------------------------------------------------------
// S1) bitonic-sort 1024-element segments, 256 threads x 4 elements.
//     Distances >=256: in-register pairs; 32..128: smem; <=16: shfl.
//     64-bit (key<<32 | idx) items.
// ---------------------------------------------------------------------------
__global__ __launch_bounds__(256) void kdm_sort_seg(const float* __restrict__ X,
                                                    const float* __restrict__ Xh) {
    const int md = blockIdx.y;
    const int d  = md & 7;
    const float* __restrict__ src = (md >> 3) ? Xh : X;
    __shared__ unsigned long long s[SEGSZ];   // 8 KB
    const int t  = threadIdx.x;
    const int e0 = blockIdx.x * SEGSZ;

    unsigned long long v[4];
    #pragma unroll
    for (int q = 0; q < 4; q++) {
        const int idx = q * 256 + t;
        v[q] = ((unsigned long long)f2sortable(src[(size_t)(e0 + idx) * KD + d]) << 32)
               | (unsigned)(e0 + idx);
    }

    #pragma unroll
    for (int k = 2; k <= SEGSZ; k <<= 1) {
        int j = k >> 1;
        // in-register passes (j = 512, 256)
        #pragma unroll
        for (int jj = 512; jj >= 256; jj >>= 1) {
            if (jj <= (k >> 1)) {
                const int dq = jj >> 8;                    // 2 or 1
                #pragma unroll
                for (int qa = 0; qa < 4; qa++) {
                    if ((qa & dq) == 0) {
                        const int qb = qa | dq;
                        const bool up = (((qa * 256 + t) & k) == 0);
                        const unsigned long long a = v[qa], b = v[qb];
                        if ((a > b) == up) { v[qa] = b; v[qb] = a; }
                    }
                }
                j = jj >> 1;
            }
        }
        // smem passes (j = 128, 64, 32)
        while (j >= 32) {
            #pragma unroll
            for (int q = 0; q < 4; q++) s[q * 256 + t] = v[q];
            __syncthreads();
            unsigned long long p[4];
            #pragma unroll
            for (int q = 0; q < 4; q++) p[q] = s[q * 256 + (t ^ j)];
            __syncthreads();
            #pragma unroll
            for (int q = 0; q < 4; q++) {
                const bool up   = (((q * 256 + t) & k) == 0);
                const bool low  = (t & j) == 0;
                const bool keepmin = (low == up);
                const bool omin = (p[q] < v[q]);
                v[q] = (keepmin == omin) ? p[q] : v[q];
            }
            j >>= 1;
        }
        // shfl passes (j <= 16)
        #pragma unroll
        for (int jj = 16; jj >= 1; jj >>= 1) {
            if (jj <= (k >> 1)) {
                #pragma unroll
                for (int q = 0; q < 4; q++) {
                    const unsigned long long o = __shfl_xor_sync(0xffffffffu, v[q], jj);
                    const bool up   = (((q * 256 + t) & k) == 0);
                    const bool low  = (t & jj) == 0;
                    const bool keepmin = (low == up);
                    const bool omin = (o < v[q]);
                    v[q] = (keepmin == omin) ? o : v[q];
                }
            }
        }
    }

    #pragma unroll
    for (int q = 0; q < 4; q++) {
        const unsigned long long r = v[q];
        g_keys[md][e0 + q * 256 + t] = (unsigned)(r >> 32);
        g_kidx[md][e0 + q * 256 + t] = (int)(unsigned)r;
    }
}

// ---------------------------------------------------------------------------
// S2) global rank per column via cross-segment binary search (proven loop
//     form: lo can reach 1024); scatter 16-bit rank to the original row.
// ---------------------------------------------------------------------------
__global__ __launch_bounds__(256) void kdm_rank() {
    const int md = blockIdx.y;
    __shared__ unsigned sk[KN];   // 32 KB
    for (int k = threadIdx.x; k < KN; k += 256) sk[k] = g_keys[md][k];
    __syncthreads();

    const int e   = blockIdx.x * 256 + threadIdx.x;
    const int s   = e >> 10;
    const int pos = e & (SEGSZ - 1);
    const unsigned key = sk[e];

    int rank = pos;
    #pragma unroll
    for (int t = 0; t < NSEG; t++) {
        if (t == s) continue;
        const unsigned* seg = sk + t * SEGSZ;
        int lo = 0, hi = SEGSZ;
        if (t < s) {  // count <= key
            while (lo < hi) { const int mid = (lo + hi) >> 1; if (seg[mid] <= key) lo = mid + 1; else hi = mid; }
        } else {      // count < key
            while (lo < hi) { const int mid = (lo + hi) >> 1; if (seg[mid] <  key) lo = mid + 1; else hi = mid; }
        }
        rank += lo;
    }
    g_rank16[md >> 3][g_kidx[md][e]][md & 7] = (unsigned short)rank;
}

// ---------------------------------------------------------------------------
// S3) pack dims 1..7 ranks (+0x400 fp16 bias) into a uint4 at the row's
//     d0-rank position. grid = (KN/256, 2).
// ---------------------------------------------------------------------------
__global__ __launch_bounds__(256) void kdm_pack() {
    const int m   = blockIdx.y;
    const int row = blockIdx.x * 256 + threadIdx.x;
    const uint4 q = *reinterpret_cast<const uint4*>(&g_rank16[m][row][0]);
    const unsigned OFF = 0x04000400u;
    const unsigned d0 = q.x & 0xffffu;
    uint4 o;
    o.x = ((q.x >> 16) | (q.y << 16)) + OFF;   // d1, d2
    o.y = ((q.y >> 16) | (q.z << 16)) + OFF;   // d3, d4
    o.z = ((q.z >> 16) | (q.w << 16)) + OFF;   // d5, d6
    o.w = ( q.w >> 16)                + OFF;   // d7, pad
    g_prow[m][d0] = o;
}

// ---------------------------------------------------------------------------
// D) triangular dominance on rank-sorted packed rows. Thread owns 4 i-rows
//    (1024-row strips); j-tiles of 64 -> 576 tiles/matrix for occupancy.
//    Strip ti has 16*(ti+1) tiles; start(ti) = 8*ti*(ti+1).
// ---------------------------------------------------------------------------
__global__ __launch_bounds__(NTHR, 6) void kdm_dom() {
    const int m = blockIdx.y;
    const int b = blockIdx.x;
    int ti = (int)(sqrtf((float)b * 0.125f + 0.25f));
    while (ti > 0 && 8 * ti * (ti + 1) > b) --ti;
    while (8 * (ti + 1) * (ti + 2) <= b) ++ti;
    const int tj = b - 8 * ti * (ti + 1);
    const int i0 = ti << 10;
    const int j0 = tj << 6;

    __shared__ uint4 sj[TJ];    // 1 KB, fp16-negated j-rows

    if (threadIdx.x < TJ) {
        uint4 v = g_prow[m][j0 + threadIdx.x];
        v.x ^= 0x80008000u; v.y ^= 0x80008000u;
        v.z ^= 0x80008000u; v.w ^= 0x80008000u;
        sj[threadIdx.x] = v;
    }

    const int ib = i0 + threadIdx.x;
    uint4 a[IPT];
    #pragma unroll
    for (int p = 0; p < IPT; p++) a[p] = g_prow[m][ib + p * NTHR];
    __syncthreads();

    unsigned neg[IPT] = {0, 0, 0, 0};

    if (j0 + TJ <= i0) {
        #pragma unroll 4
        for (int j = 0; j < TJ; j++) {
            const uint4 bv = sj[j];
            #pragma unroll
            for (int p = 0; p < IPT; p++) {
                const unsigned x0 = hadd2(a[p].x, bv.x);
                const unsigned x1 = hadd2(a[p].y, bv.y);
                const unsigned x2 = hadd2(a[p].z, bv.z);
                const unsigned x3 = hadd2(a[p].w, bv.w);
                const unsigned o  = x0 | x1 | x2;
                const unsigned sb = (o | x3) & 0x80008000u;
                if (sb) neg[p]++;
            }
        }
    } else {
        int lim[IPT];
        #pragma unroll
        for (int p = 0; p < IPT; p++) lim[p] = ib + p * NTHR - j0;
        #pragma unroll 4
        for (int j = 0; j < TJ; j++) {
            const uint4 bv = sj[j];
            #pragma unroll
            for (int p = 0; p < IPT; p++) {
                const unsigned x0 = hadd2(a[p].x, bv.x);
                const unsigned x1 = hadd2(a[p].y, bv.y);
                const unsigned x2 = hadd2(a[p].z, bv.z);
                const unsigned x3 = hadd2(a[p].w, bv.w);
                const unsigned o  = x0 | x1 | x2;
                const unsigned sb = (o | x3) & 0x80008000u;
                neg[p] += min(sb, 1u) | (unsigned)(j >= lim[p]);
            }
        }
    }

    #pragma unroll
    for (int p = 0; p < IPT; p++)
        atomicAdd(&g_counts[m * KN + ib + p * NTHR], (int)neg[p]);
}

// ---------------------------------------------------------------------------
// FH) fused histogram + finalize. 16 blocks histogram into g_hd with
//     warp-aggregated atomics; the LAST block to arrive runs the W1 scan.
//     Order-independent result -> deterministic. Re-zeroes consumed scratch.
// ---------------------------------------------------------------------------
__global__ __launch_bounds__(1024) void kdm_finh(float* __restrict__ out) {
    const int tid = threadIdx.x, lane = tid & 31, wid = tid >> 5;

    {   // histogram phase
        const int slot = blockIdx.x * 1024 + tid;
        const int neg  = g_counts[slot];
        g_counts[slot] = 0;
        const int i = slot & (KN - 1);
        const int v = (((i >> 10) + 1) << 10) - neg;   // dominated count
        const int delta = (slot >= KN) ? -1 : 1;
        const unsigned mask = __match_any_sync(0xffffffffu, v);
        if ((int)(__ffs(mask) - 1) == lane)
            atomicAdd(&g_hd[v], delta * __popc(mask));
    }

    __threadfence();
    __syncthreads();
    __shared__ bool s_last;
    if (tid == 0) s_last = (atomicAdd(&g_ctr, 1u) == gridDim.x - 1);
    __syncthreads();
    if (!s_last) return;
    __threadfence();   // acquire all blocks' g_hd updates

    __shared__ int wsum[32];
    const int base = tid * 8;
    int d[8], tot = 0;
    #pragma unroll
    for (int k = 0; k < 8; k++) {
        d[k] = g_hd[base + k];
        g_hd[base + k] = 0;
        tot += d[k];
    }

    int v = tot;
    #pragma unroll
    for (int off = 1; off < 32; off <<= 1) {
        const int n = __shfl_up_sync(0xffffffffu, v, off);
        if (lane >= off) v += n;
    }
    if (lane == 31) wsum[wid] = v;
    __syncthreads();
    if (wid == 0) {
        int w = wsum[lane];
        #pragma unroll
        for (int off = 1; off < 32; off <<= 1) {
            const int n = __shfl_up_sync(0xffffffffu, w, off);
            if (lane >= off) w += n;
        }
        wsum[lane] = w;
    }
    __syncthreads();

    const int excl = v - tot + (wid ? wsum[wid - 1] : 0);
    int run = excl, acc = 0;
    #pragma unroll
    for (int k = 0; k < 8; k++) {
        run += d[k];
        acc += (run >= 0) ? run : -run;
    }

    #pragma unroll
    for (int off = 16; off; off >>= 1) acc += __shfl_down_sync(0xffffffffu, acc, off);
    __syncthreads();
    if (lane == 0) wsum[wid] = acc;
    __syncthreads();
    if (wid == 0) {
        int r = wsum[lane];
        #pragma unroll
        for (int off = 16; off; off >>= 1) r += __shfl_down_sync(0xffffffffu, r, off);
        if (lane == 0) {
            out[0] = (float)r / ((float)KN * (float)(KN - 1));
            g_ctr = 0;   // reset for next graph replay
        }
    }
}

// ---------------------------------------------------------------------------
extern "C" void kernel_launch(void* const* d_in, const int* in_sizes, int n_in,
                              void* d_out, int out_size) {
    const float* X  = (const float*)d_in[0];
    const float* Xh = (const float*)d_in[1];
    float* out = (float*)d_out;

    kdm_sort_seg<<<dim3(NSEG, 16),     256 >>>(X, Xh);
    kdm_rank    <<<dim3(KN / 256, 16), 256 >>>();
    kdm_pack    <<<dim3(KN / 256, 2),  256 >>>();
    kdm_dom     <<<dim3(NTILES, 2),    NTHR>>>();
    kdm_finh    <<<2 * KN / 1024,      1024>>>(out);
}